// round 9
// baseline (speedup 1.0000x reference)
#include <cuda_runtime.h>
#include <cstdint>

#define NBLK    128
#define FEAT    32
#define THREADS 128
#define NBATCH  1024

#define NCHUNK   8            // k-chunks of 16
#define CHUNK_K  16
#define ASTRIDE  20           // floats per chunk row (16 + 4 pad): 20*gid+tig bijective mod 32
#define ACH_FLOATS (NBLK * ASTRIDE)      // 2560 floats = 10240 B per stage buffer
#define NSTAGE   2
#define B_OFF    (NSTAGE * ACH_FLOATS)   // 5120 floats
#define SMEM_FLOATS (B_OFF + NBLK * 32)  // + 4096 = 9216 floats = 36864 B

__device__ int g_idx[NBATCH];

// Resolve index dtype defensively (jax silently downcasts int64->int32 without x64).
__global__ void resolve_idx_kernel(const int* __restrict__ raw) {
    __shared__ int odd_nonzero;
    const int t = threadIdx.x;  // 1024 threads
    if (t == 0) odd_nonzero = 0;
    __syncthreads();
    int v = raw[t];
    if ((t & 1) && v != 0) odd_nonzero = 1;   // benign race, same value
    __syncthreads();
    int g = odd_nonzero ? raw[t] : raw[2 * t];
    if (g < 0) g = 0;
    if (g >= 1024) g = 1023;
    g_idx[t] = g;
}

// m16n8k8 TF32 mma: D += A*B, fp32 accumulate. HW ignores operand low 13 bits.
__device__ __forceinline__ void mma_tf32(float* d, uint32_t a0, uint32_t a1,
                                         uint32_t a2, uint32_t a3,
                                         uint32_t b0, uint32_t b1) {
    asm volatile(
        "mma.sync.aligned.m16n8k8.row.col.f32.tf32.tf32.f32 "
        "{%0,%1,%2,%3}, {%4,%5,%6,%7}, {%8,%9}, {%0,%1,%2,%3};"
        : "+f"(d[0]), "+f"(d[1]), "+f"(d[2]), "+f"(d[3])
        : "r"(a0), "r"(a1), "r"(a2), "r"(a3), "r"(b0), "r"(b1));
}

__device__ __forceinline__ uint32_t f2u(float f) { return __float_as_uint(f); }
__device__ __forceinline__ uint32_t smem_u32(const void* p) {
    uint32_t a;
    asm("{ .reg .u64 t; cvta.to.shared.u64 t, %1; cvt.u32.u64 %0, t; }" : "=r"(a) : "l"(p));
    return a;
}
__device__ __forceinline__ void cp16(uint32_t dst, const void* src) {
    asm volatile("cp.async.cg.shared.global [%0], [%1], 16;" :: "r"(dst), "l"(src));
}
#define CP_COMMIT()  asm volatile("cp.async.commit_group;" ::: "memory")
#define CP_WAIT(n)   asm volatile("cp.async.wait_group %0;" :: "n"(n) : "memory")

// Per CTA: out[128,32] = W[idx[b]] @ x[b] via 3xTF32-split mma.sync.
// W streamed in eight k=16 chunks through a 2-stage cp.async ring (36.9KB smem
// total with XOR-swizzled B) -> 6 CTAs/SM resident, 24 warps.
// D = a_hi*b_hi + a_lo*b_hi + a_hi*b_lo, residual ~2^-20.
__global__ void __launch_bounds__(THREADS, 6) bmm_mma_kernel(
    const float* __restrict__ inp,
    const float* __restrict__ W,
    float* __restrict__ out)
{
    extern __shared__ float smem[];
    float* Bs = smem + B_OFF;

    const int blk = blockIdx.x;
    const int tid = threadIdx.x;
    const int wid = tid >> 5;
    const int lid = tid & 31;
    const int gid = lid >> 2;         // groupID 0..7
    const int tig = lid & 3;          // thread-in-group 0..3

    const int g = g_idx[blk];
    const float* Wg = W + (long long)g * (NBLK * NBLK);
    const float4* xg = (const float4*)(inp + (long long)blk * NBLK * FEAT);

    // One chunk = 128 rows x 16 floats = 512 x 16B; 4 cp.async per thread.
    #define ISSUE_CHUNK(ck, buf) do {                                            \
        const float* srcb = Wg + (ck) * CHUNK_K;                                 \
        float* dstb = smem + (buf) * ACH_FLOATS;                                 \
        _Pragma("unroll")                                                        \
        for (int it = 0; it < 4; ++it) {                                         \
            int c = tid + THREADS * it;                                          \
            int row = c >> 2, slot = c & 3;                                      \
            cp16(smem_u32(dstb + row * ASTRIDE + slot * 4),                      \
                 srcb + row * NBLK + slot * 4);                                  \
        }                                                                        \
        CP_COMMIT();                                                             \
    } while (0)

    ISSUE_CHUNK(0, 0);
    ISSUE_CHUNK(1, 1);

    // ---- Stage B (x): word = k*32 + (col ^ ((k&3)*8)), 16KB, conflict-free ----
    #pragma unroll
    for (int it = 0; it < 8; ++it) {
        int q = tid + THREADS * it;            // k = q>>3, f0 = (q&7)*4
        float4 v = xg[q];
        int k  = q >> 3;
        int f0 = (q & 7) * 4;
        *(float4*)(Bs + k * 32 + (f0 ^ ((k & 3) * 8))) = v;
    }

    // Warp w computes rows [w*32, w*32+32) x all 32 cols: 2 m-tiles x 4 n-tiles.
    const int R = wid * 32;

    float d[2][4][4];
    #pragma unroll
    for (int mt = 0; mt < 2; ++mt)
        #pragma unroll
        for (int nt = 0; nt < 4; ++nt)
            #pragma unroll
            for (int e = 0; e < 4; ++e) d[mt][nt][e] = 0.0f;

    // B fragment columns for this thread: bank-bijective (gid | 8*(nt^tig))
    int bcol[4];
    #pragma unroll
    for (int nt = 0; nt < 4; ++nt) bcol[nt] = (nt * 8 + gid) ^ (tig * 8);

    const uint32_t HMASK = 0xFFFFE000u;  // tf32-visible bits

    #pragma unroll
    for (int ck = 0; ck < NCHUNK; ++ck) {
        if (ck < NCHUNK - 1) { CP_WAIT(1); } else { CP_WAIT(0); }
        __syncthreads();   // chunk ck visible to all warps

        const float* a_base = smem + (ck & 1) * ACH_FLOATS + (R + gid) * ASTRIDE + tig;

        #pragma unroll
        for (int s = 0; s < 2; ++s) {                 // ks = ck*2 + s
            float a[2][4];
            #pragma unroll
            for (int mt = 0; mt < 2; ++mt) {
                const float* p = a_base + mt * (16 * ASTRIDE) + s * 8;
                a[mt][0] = p[0];
                a[mt][1] = p[8 * ASTRIDE];
                a[mt][2] = p[4];
                a[mt][3] = p[8 * ASTRIDE + 4];
            }
            float b[4][2];
            const float* brow = Bs + ((ck * 2 + s) * 8 + tig) * 32;
            #pragma unroll
            for (int nt = 0; nt < 4; ++nt) {
                b[nt][0] = brow[bcol[nt]];
                b[nt][1] = brow[128 + bcol[nt]];       // k+4: same (k&3), same col map
            }
            uint32_t al[2][4], bl[4][2];
            #pragma unroll
            for (int mt = 0; mt < 2; ++mt)
                #pragma unroll
                for (int e = 0; e < 4; ++e)
                    al[mt][e] = f2u(a[mt][e] - __uint_as_float(f2u(a[mt][e]) & HMASK));
            #pragma unroll
            for (int nt = 0; nt < 4; ++nt)
                #pragma unroll
                for (int e = 0; e < 2; ++e)
                    bl[nt][e] = f2u(b[nt][e] - __uint_as_float(f2u(b[nt][e]) & HMASK));

            #pragma unroll
            for (int mt = 0; mt < 2; ++mt) {
                #pragma unroll
                for (int nt = 0; nt < 4; ++nt) {
                    mma_tf32(d[mt][nt], f2u(a[mt][0]), f2u(a[mt][1]), f2u(a[mt][2]), f2u(a[mt][3]),
                             f2u(b[nt][0]), f2u(b[nt][1]));
                    mma_tf32(d[mt][nt], al[mt][0], al[mt][1], al[mt][2], al[mt][3],
                             f2u(b[nt][0]), f2u(b[nt][1]));
                    mma_tf32(d[mt][nt], f2u(a[mt][0]), f2u(a[mt][1]), f2u(a[mt][2]), f2u(a[mt][3]),
                             bl[nt][0], bl[nt][1]);
                }
            }
        }

        __syncthreads();   // all warps done with buffer ck&1
        if (ck + 2 < NCHUNK) ISSUE_CHUNK(ck + 2, ck & 1);
    }

    // ---- Epilogue: write D fragments straight to gmem (float2 per pair) ----
    float* ob = out + (long long)blk * NBLK * FEAT;
    #pragma unroll
    for (int mt = 0; mt < 2; ++mt) {
        const int r0 = R + mt * 16 + gid;
        #pragma unroll
        for (int nt = 0; nt < 4; ++nt) {
            const int c = nt * 8 + tig * 2;
            *(float2*)(ob + r0 * FEAT + c)       = make_float2(d[mt][nt][0], d[mt][nt][1]);
            *(float2*)(ob + (r0 + 8) * FEAT + c) = make_float2(d[mt][nt][2], d[mt][nt][3]);
        }
    }
}

extern "C" void kernel_launch(void* const* d_in, const int* in_sizes, int n_in,
                              void* d_out, int out_size) {
    // Select pointers by element count (robust to metadata ordering).
    const float* inp = nullptr;
    const float* W   = nullptr;
    const void*  idx = nullptr;
    for (int i = 0; i < n_in; ++i) {
        if      (in_sizes[i] == 4194304)  inp = (const float*)d_in[i];
        else if (in_sizes[i] == 16777216) W   = (const float*)d_in[i];
        else if (in_sizes[i] == 1024)     idx = d_in[i];
    }

    resolve_idx_kernel<<<1, NBATCH>>>((const int*)idx);

    const size_t smem_bytes = SMEM_FLOATS * sizeof(float);  // 36864
    cudaFuncSetAttribute(bmm_mma_kernel, cudaFuncAttributeMaxDynamicSharedMemorySize,
                         (int)smem_bytes);
    bmm_mma_kernel<<<NBATCH, THREADS, smem_bytes>>>(inp, W, (float*)d_out);
}

// round 10
// speedup vs baseline: 1.0013x; 1.0013x over previous
#include <cuda_runtime.h>
#include <cstdint>

#define NBLK    128
#define FEAT    32
#define THREADS 128
#define NBATCH  1024

#define NCHUNK   8            // k-chunks of 16
#define CHUNK_K  16
#define ASTRIDE  20           // floats per chunk row (16 + 4 pad): 20*gid+tig bijective mod 32
#define ACH_FLOATS (NBLK * ASTRIDE)      // 2560 floats = 10240 B per stage buffer
#define NSTAGE   3
#define BSTRIDE  40           // floats per B row (32 + 8 pad): 8*tig+gid bijective
#define B_OFF    (NSTAGE * ACH_FLOATS)   // 7680 floats
#define SMEM_FLOATS (B_OFF + NBLK * BSTRIDE)  // 12800 floats = 51200 B

__device__ int g_idx[NBATCH];

// Resolve index dtype defensively (jax silently downcasts int64->int32 without x64).
__global__ void resolve_idx_kernel(const int* __restrict__ raw) {
    __shared__ int odd_nonzero;
    const int t = threadIdx.x;  // 1024 threads
    if (t == 0) odd_nonzero = 0;
    __syncthreads();
    int v = raw[t];
    if ((t & 1) && v != 0) odd_nonzero = 1;   // benign race, same value
    __syncthreads();
    int g = odd_nonzero ? raw[t] : raw[2 * t];
    if (g < 0) g = 0;
    if (g >= 1024) g = 1023;
    g_idx[t] = g;
}

// m16n8k8 TF32 mma: D += A*B, fp32 accumulate. HW ignores operand low 13 bits.
// NOT volatile: the "+f" accumulator constraints carry the true dependencies,
// so ptxas may schedule/interleave independent MMAs to hide HMMA latency.
__device__ __forceinline__ void mma_tf32(float* d, uint32_t a0, uint32_t a1,
                                         uint32_t a2, uint32_t a3,
                                         uint32_t b0, uint32_t b1) {
    asm("mma.sync.aligned.m16n8k8.row.col.f32.tf32.tf32.f32 "
        "{%0,%1,%2,%3}, {%4,%5,%6,%7}, {%8,%9}, {%0,%1,%2,%3};"
        : "+f"(d[0]), "+f"(d[1]), "+f"(d[2]), "+f"(d[3])
        : "r"(a0), "r"(a1), "r"(a2), "r"(a3), "r"(b0), "r"(b1));
}

__device__ __forceinline__ uint32_t f2u(float f) { return __float_as_uint(f); }
__device__ __forceinline__ uint32_t smem_u32(const void* p) {
    uint32_t a;
    asm("{ .reg .u64 t; cvta.to.shared.u64 t, %1; cvt.u32.u64 %0, t; }" : "=r"(a) : "l"(p));
    return a;
}
__device__ __forceinline__ void cp16(uint32_t dst, const void* src) {
    asm volatile("cp.async.cg.shared.global [%0], [%1], 16;" :: "r"(dst), "l"(src));
}
#define CP_COMMIT()  asm volatile("cp.async.commit_group;" ::: "memory")
#define CP_WAIT(n)   asm volatile("cp.async.wait_group %0;" :: "n"(n) : "memory")

// Per CTA: out[128,32] = W[idx[b]] @ x[b] via 3xTF32-split mma.sync.
// W streamed in eight k=16 chunks through a 3-stage cp.async ring; one barrier
// per chunk, issue of chunk c+2 ahead of compute of chunk c. 51.2KB -> 4 CTAs/SM.
// MMAs emitted PASS-MAJOR (all hi*hi, then all lo_a*hi, then all hi*lo_b) so
// each accumulator's dependent reuse distance is 8 MMAs, not 1.
// D = a_hi*b_hi + a_lo*b_hi + a_hi*b_lo, residual ~2^-21.
__global__ void __launch_bounds__(THREADS, 4) bmm_mma_kernel(
    const float* __restrict__ inp,
    const float* __restrict__ W,
    float* __restrict__ out)
{
    extern __shared__ float smem[];
    float* Bs = smem + B_OFF;

    const int blk = blockIdx.x;
    const int tid = threadIdx.x;
    const int wid = tid >> 5;
    const int lid = tid & 31;
    const int gid = lid >> 2;         // groupID 0..7
    const int tig = lid & 3;          // thread-in-group 0..3

    const int g = g_idx[blk];
    const float* Wg = W + (long long)g * (NBLK * NBLK);
    const float4* xg = (const float4*)(inp + (long long)blk * NBLK * FEAT);

    // One chunk = 128 rows x 16 floats = 512 x 16B; 4 cp.async per thread.
    #define ISSUE_CHUNK(ck, buf) do {                                            \
        const float* srcb = Wg + (ck) * CHUNK_K;                                 \
        float* dstb = smem + (buf) * ACH_FLOATS;                                 \
        _Pragma("unroll")                                                        \
        for (int it = 0; it < 4; ++it) {                                         \
            int c = tid + THREADS * it;                                          \
            int row = c >> 2, slot = c & 3;                                      \
            cp16(smem_u32(dstb + row * ASTRIDE + slot * 4),                      \
                 srcb + row * NBLK + slot * 4);                                  \
        }                                                                        \
        CP_COMMIT();                                                             \
    } while (0)

    ISSUE_CHUNK(0, 0);
    ISSUE_CHUNK(1, 1);

    // ---- Stage B (x): [k][n] rows padded to 40 floats ----
    #pragma unroll
    for (int it = 0; it < 8; ++it) {
        int q = tid + THREADS * it;            // k = q>>3, f0 = (q&7)*4
        float4 v = xg[q];
        *(float4*)(Bs + (q >> 3) * BSTRIDE + (q & 7) * 4) = v;
    }

    // Warp w computes rows [w*32, w*32+32) x all 32 cols: 2 m-tiles x 4 n-tiles.
    const int R = wid * 32;

    float d[2][4][4];
    #pragma unroll
    for (int mt = 0; mt < 2; ++mt)
        #pragma unroll
        for (int nt = 0; nt < 4; ++nt)
            #pragma unroll
            for (int e = 0; e < 4; ++e) d[mt][nt][e] = 0.0f;

    const float* b_base = Bs + tig * BSTRIDE + gid;
    const uint32_t HMASK = 0xFFFFE000u;  // tf32-visible bits

    #pragma unroll
    for (int ck = 0; ck < NCHUNK; ++ck) {
        if (ck < NCHUNK - 1) { CP_WAIT(1); } else { CP_WAIT(0); }
        __syncthreads();   // chunk ck visible; buf (ck+2)%3's old chunk consumed

        if (ck + 2 < NCHUNK) ISSUE_CHUNK(ck + 2, (ck + 2) % NSTAGE);

        const float* a_base = smem + (ck % NSTAGE) * ACH_FLOATS + (R + gid) * ASTRIDE + tig;

        #pragma unroll
        for (int s = 0; s < 2; ++s) {                 // ks = ck*2 + s
            float a[2][4];
            #pragma unroll
            for (int mt = 0; mt < 2; ++mt) {
                const float* p = a_base + mt * (16 * ASTRIDE) + s * 8;
                a[mt][0] = p[0];
                a[mt][1] = p[8 * ASTRIDE];
                a[mt][2] = p[4];
                a[mt][3] = p[8 * ASTRIDE + 4];
            }
            float b[4][2];
            #pragma unroll
            for (int nt = 0; nt < 4; ++nt) {
                const float* p = b_base + (ck * 2 + s) * (8 * BSTRIDE) + nt * 8;
                b[nt][0] = p[0];
                b[nt][1] = p[4 * BSTRIDE];
            }
            uint32_t al[2][4], bl[4][2];
            #pragma unroll
            for (int mt = 0; mt < 2; ++mt)
                #pragma unroll
                for (int e = 0; e < 4; ++e)
                    al[mt][e] = f2u(a[mt][e] - __uint_as_float(f2u(a[mt][e]) & HMASK));
            #pragma unroll
            for (int nt = 0; nt < 4; ++nt)
                #pragma unroll
                for (int e = 0; e < 2; ++e)
                    bl[nt][e] = f2u(b[nt][e] - __uint_as_float(f2u(b[nt][e]) & HMASK));

            // ---- Pass-major emission: 8 independent MMAs between reuses ----
            #pragma unroll
            for (int mt = 0; mt < 2; ++mt)
                #pragma unroll
                for (int nt = 0; nt < 4; ++nt)
                    mma_tf32(d[mt][nt], f2u(a[mt][0]), f2u(a[mt][1]), f2u(a[mt][2]), f2u(a[mt][3]),
                             f2u(b[nt][0]), f2u(b[nt][1]));
            #pragma unroll
            for (int mt = 0; mt < 2; ++mt)
                #pragma unroll
                for (int nt = 0; nt < 4; ++nt)
                    mma_tf32(d[mt][nt], al[mt][0], al[mt][1], al[mt][2], al[mt][3],
                             f2u(b[nt][0]), f2u(b[nt][1]));
            #pragma unroll
            for (int mt = 0; mt < 2; ++mt)
                #pragma unroll
                for (int nt = 0; nt < 4; ++nt)
                    mma_tf32(d[mt][nt], f2u(a[mt][0]), f2u(a[mt][1]), f2u(a[mt][2]), f2u(a[mt][3]),
                             bl[nt][0], bl[nt][1]);
        }
    }

    // ---- Epilogue: write D fragments straight to gmem (float2 per pair) ----
    float* ob = out + (long long)blk * NBLK * FEAT;
    #pragma unroll
    for (int mt = 0; mt < 2; ++mt) {
        const int r0 = R + mt * 16 + gid;
        #pragma unroll
        for (int nt = 0; nt < 4; ++nt) {
            const int c = nt * 8 + tig * 2;
            *(float2*)(ob + r0 * FEAT + c)       = make_float2(d[mt][nt][0], d[mt][nt][1]);
            *(float2*)(ob + (r0 + 8) * FEAT + c) = make_float2(d[mt][nt][2], d[mt][nt][3]);
        }
    }
}

extern "C" void kernel_launch(void* const* d_in, const int* in_sizes, int n_in,
                              void* d_out, int out_size) {
    // Select pointers by element count (robust to metadata ordering).
    const float* inp = nullptr;
    const float* W   = nullptr;
    const void*  idx = nullptr;
    for (int i = 0; i < n_in; ++i) {
        if      (in_sizes[i] == 4194304)  inp = (const float*)d_in[i];
        else if (in_sizes[i] == 16777216) W   = (const float*)d_in[i];
        else if (in_sizes[i] == 1024)     idx = d_in[i];
    }

    resolve_idx_kernel<<<1, NBATCH>>>((const int*)idx);

    const size_t smem_bytes = SMEM_FLOATS * sizeof(float);  // 51200
    cudaFuncSetAttribute(bmm_mma_kernel, cudaFuncAttributeMaxDynamicSharedMemorySize,
                         (int)smem_bytes);
    bmm_mma_kernel<<<NBATCH, THREADS, smem_bytes>>>(inp, W, (float*)d_out);
}

// round 11
// speedup vs baseline: 1.0880x; 1.0867x over previous
#include <cuda_runtime.h>
#include <cstdint>

#define NBLK    128
#define FEAT    32
#define THREADS 128
#define NBATCH  1024

#define NCHUNK   8            // k-chunks of 16 (one m16n8k16 step each)
#define CHUNK_K  16
#define ASTRIDE  20           // floats per chunk row (16 + 4 pad)
#define ACH_FLOATS (NBLK * ASTRIDE)      // 2560 floats = 10240 B per stage buffer
#define NSTAGE   3
#define BSTRIDE  40           // floats per B row (32 + 8 pad)
#define B_OFF    (NSTAGE * ACH_FLOATS)   // 7680 floats
#define SMEM_FLOATS (B_OFF + NBLK * BSTRIDE)  // 12800 floats = 51200 B

__device__ int g_idx[NBATCH];

// Resolve index dtype defensively (jax silently downcasts int64->int32 without x64).
__global__ void resolve_idx_kernel(const int* __restrict__ raw) {
    __shared__ int odd_nonzero;
    const int t = threadIdx.x;  // 1024 threads
    if (t == 0) odd_nonzero = 0;
    __syncthreads();
    int v = raw[t];
    if ((t & 1) && v != 0) odd_nonzero = 1;   // benign race, same value
    __syncthreads();
    int g = odd_nonzero ? raw[t] : raw[2 * t];
    if (g < 0) g = 0;
    if (g >= 1024) g = 1023;
    g_idx[t] = g;
}

// m16n8k16 bf16 mma: D += A*B, fp32 accumulate. Full-rate HMMA, K=16/instr.
__device__ __forceinline__ void mma_bf16(float* d, uint32_t a0, uint32_t a1,
                                         uint32_t a2, uint32_t a3,
                                         uint32_t b0, uint32_t b1) {
    asm("mma.sync.aligned.m16n8k16.row.col.f32.bf16.bf16.f32 "
        "{%0,%1,%2,%3}, {%4,%5,%6,%7}, {%8,%9}, {%0,%1,%2,%3};"
        : "+f"(d[0]), "+f"(d[1]), "+f"(d[2]), "+f"(d[3])
        : "r"(a0), "r"(a1), "r"(a2), "r"(a3), "r"(b0), "r"(b1));
}

// pack2bf16(lo=x, hi=y): cvt.rn.bf16x2.f32 d, a(hi), b(lo)
__device__ __forceinline__ uint32_t pack_bf16(float x, float y) {
    uint32_t d;
    asm("cvt.rn.bf16x2.f32 %0, %1, %2;" : "=r"(d) : "f"(y), "f"(x));
    return d;
}
// Split one fp32 pair: h = packed bf16(hi parts), l = packed bf16 of exact residuals.
__device__ __forceinline__ void split_pair(float x, float y, uint32_t& h, uint32_t& l) {
    h = pack_bf16(x, y);
    float hx = __uint_as_float(h << 16);          // bf16(x) as float
    float hy = __uint_as_float(h & 0xFFFF0000u);  // bf16(y) as float
    l = pack_bf16(x - hx, y - hy);                // residuals (exact in fp32)
}

__device__ __forceinline__ uint32_t smem_u32(const void* p) {
    uint32_t a;
    asm("{ .reg .u64 t; cvta.to.shared.u64 t, %1; cvt.u32.u64 %0, t; }" : "=r"(a) : "l"(p));
    return a;
}
__device__ __forceinline__ void cp16(uint32_t dst, const void* src) {
    asm volatile("cp.async.cg.shared.global [%0], [%1], 16;" :: "r"(dst), "l"(src));
}
#define CP_COMMIT()  asm volatile("cp.async.commit_group;" ::: "memory")
#define CP_WAIT(n)   asm volatile("cp.async.wait_group %0;" :: "n"(n) : "memory")

// Per CTA: out[128,32] = W[idx[b]] @ x[b] via 3xBF16-split m16n8k16 mma.sync.
// D = ah*bh + al*bh + ah*bl (bf16 2-term split, residual ~2^-18 per element).
// W streamed in eight k=16 chunks through a 3-stage cp.async ring (R8 skeleton,
// 51.2KB smem -> 4 CTAs/SM); fp32 in smem, bf16 split done in registers.
// Half the MMA instructions of the tf32 version at full HMMA rate.
__global__ void __launch_bounds__(THREADS, 4) bmm_mma_kernel(
    const float* __restrict__ inp,
    const float* __restrict__ W,
    float* __restrict__ out)
{
    extern __shared__ float smem[];
    float* Bs = smem + B_OFF;

    const int blk = blockIdx.x;
    const int tid = threadIdx.x;
    const int wid = tid >> 5;
    const int lid = tid & 31;
    const int gid = lid >> 2;         // groupID 0..7
    const int tig = lid & 3;          // thread-in-group 0..3

    const int g = g_idx[blk];
    const float* Wg = W + (long long)g * (NBLK * NBLK);
    const float4* xg = (const float4*)(inp + (long long)blk * NBLK * FEAT);

    // One chunk = 128 rows x 16 floats = 512 x 16B; 4 cp.async per thread.
    #define ISSUE_CHUNK(ck, buf) do {                                            \
        const float* srcb = Wg + (ck) * CHUNK_K;                                 \
        float* dstb = smem + (buf) * ACH_FLOATS;                                 \
        _Pragma("unroll")                                                        \
        for (int it = 0; it < 4; ++it) {                                         \
            int c = tid + THREADS * it;                                          \
            int row = c >> 2, slot = c & 3;                                      \
            cp16(smem_u32(dstb + row * ASTRIDE + slot * 4),                      \
                 srcb + row * NBLK + slot * 4);                                  \
        }                                                                        \
        CP_COMMIT();                                                             \
    } while (0)

    ISSUE_CHUNK(0, 0);
    ISSUE_CHUNK(1, 1);

    // ---- Stage B (x): [k][n] rows padded to 40 floats, fp32 ----
    #pragma unroll
    for (int it = 0; it < 8; ++it) {
        int q = tid + THREADS * it;            // k = q>>3, f0 = (q&7)*4
        float4 v = xg[q];
        *(float4*)(Bs + (q >> 3) * BSTRIDE + (q & 7) * 4) = v;
    }

    // Warp w computes rows [w*32, w*32+32) x all 32 cols: 2 m-tiles x 4 n-tiles.
    const int R = wid * 32;

    float d[2][4][4];
    #pragma unroll
    for (int mt = 0; mt < 2; ++mt)
        #pragma unroll
        for (int nt = 0; nt < 4; ++nt)
            #pragma unroll
            for (int e = 0; e < 4; ++e) d[mt][nt][e] = 0.0f;

    const uint32_t a_row = R + gid;

    #pragma unroll
    for (int ck = 0; ck < NCHUNK; ++ck) {
        if (ck < NCHUNK - 1) { CP_WAIT(1); } else { CP_WAIT(0); }
        __syncthreads();   // chunk ck visible; buf (ck+2)%3's old chunk consumed

        if (ck + 2 < NCHUNK) ISSUE_CHUNK(ck + 2, (ck + 2) % NSTAGE);

        // ---- A fragments (m16n8k16): rows {r0, r0+8}, cols {2tig,2tig+1}, {+8} ----
        const float* a_base = smem + (ck % NSTAGE) * ACH_FLOATS
                              + a_row * ASTRIDE + 2 * tig;
        uint32_t ah[2][4], al[2][4];
        #pragma unroll
        for (int mt = 0; mt < 2; ++mt) {
            const float* p = a_base + mt * (16 * ASTRIDE);
            float2 v0 = *(const float2*)(p);                    // (r0,   k0,k0+1)
            float2 v1 = *(const float2*)(p + 8 * ASTRIDE);      // (r0+8, k0,k0+1)
            float2 v2 = *(const float2*)(p + 8);                // (r0,   k0+8,k0+9)
            float2 v3 = *(const float2*)(p + 8 * ASTRIDE + 8);  // (r0+8, k0+8,k0+9)
            split_pair(v0.x, v0.y, ah[mt][0], al[mt][0]);
            split_pair(v1.x, v1.y, ah[mt][1], al[mt][1]);
            split_pair(v2.x, v2.y, ah[mt][2], al[mt][2]);
            split_pair(v3.x, v3.y, ah[mt][3], al[mt][3]);
        }

        // ---- B fragments: b0 = (k=2tig,2tig+1; n), b1 = (k+8; n), n = nt*8+gid ----
        const float* bk = Bs + (ck * CHUNK_K + 2 * tig) * BSTRIDE + gid;
        uint32_t bh[4][2], bl[4][2];
        #pragma unroll
        for (int nt = 0; nt < 4; ++nt) {
            const float* p = bk + nt * 8;
            float x0 = p[0],            y0 = p[BSTRIDE];        // k0, k0+1
            float x1 = p[8 * BSTRIDE],  y1 = p[9 * BSTRIDE];    // k0+8, k0+9
            split_pair(x0, y0, bh[nt][0], bl[nt][0]);
            split_pair(x1, y1, bh[nt][1], bl[nt][1]);
        }

        // ---- Pass-major emission: hh, then al*bh, then ah*bl ----
        #pragma unroll
        for (int mt = 0; mt < 2; ++mt)
            #pragma unroll
            for (int nt = 0; nt < 4; ++nt)
                mma_bf16(d[mt][nt], ah[mt][0], ah[mt][1], ah[mt][2], ah[mt][3],
                         bh[nt][0], bh[nt][1]);
        #pragma unroll
        for (int mt = 0; mt < 2; ++mt)
            #pragma unroll
            for (int nt = 0; nt < 4; ++nt)
                mma_bf16(d[mt][nt], al[mt][0], al[mt][1], al[mt][2], al[mt][3],
                         bh[nt][0], bh[nt][1]);
        #pragma unroll
        for (int mt = 0; mt < 2; ++mt)
            #pragma unroll
            for (int nt = 0; nt < 4; ++nt)
                mma_bf16(d[mt][nt], ah[mt][0], ah[mt][1], ah[mt][2], ah[mt][3],
                         bl[nt][0], bl[nt][1]);
    }

    // ---- Epilogue: write D fragments straight to gmem (float2 per pair) ----
    float* ob = out + (long long)blk * NBLK * FEAT;
    #pragma unroll
    for (int mt = 0; mt < 2; ++mt) {
        const int r0 = R + mt * 16 + gid;
        #pragma unroll
        for (int nt = 0; nt < 4; ++nt) {
            const int c = nt * 8 + tig * 2;
            *(float2*)(ob + r0 * FEAT + c)       = make_float2(d[mt][nt][0], d[mt][nt][1]);
            *(float2*)(ob + (r0 + 8) * FEAT + c) = make_float2(d[mt][nt][2], d[mt][nt][3]);
        }
    }
}

extern "C" void kernel_launch(void* const* d_in, const int* in_sizes, int n_in,
                              void* d_out, int out_size) {
    // Select pointers by element count (robust to metadata ordering).
    const float* inp = nullptr;
    const float* W   = nullptr;
    const void*  idx = nullptr;
    for (int i = 0; i < n_in; ++i) {
        if      (in_sizes[i] == 4194304)  inp = (const float*)d_in[i];
        else if (in_sizes[i] == 16777216) W   = (const float*)d_in[i];
        else if (in_sizes[i] == 1024)     idx = d_in[i];
    }

    resolve_idx_kernel<<<1, NBATCH>>>((const int*)idx);

    const size_t smem_bytes = SMEM_FLOATS * sizeof(float);  // 51200
    cudaFuncSetAttribute(bmm_mma_kernel, cudaFuncAttributeMaxDynamicSharedMemorySize,
                         (int)smem_bytes);
    bmm_mma_kernel<<<NBATCH, THREADS, smem_bytes>>>(inp, W, (float*)d_out);
}

// round 12
// speedup vs baseline: 1.1895x; 1.0932x over previous
#include <cuda_runtime.h>
#include <cstdint>

#define NBLK    128
#define FEAT    32
#define THREADS 128
#define NBATCH  1024

#define NCHUNK   8            // k-chunks of 16 (one m16n8k16 step each)
#define CHUNK_K  16
#define ASTRIDE  20           // floats per A chunk row (16 + 4 pad)
#define ACH_FLOATS (NBLK * ASTRIDE)      // 2560 floats = 10240 B per stage buffer
#define NSTAGE   3
#define A_BYTES  (NSTAGE * ACH_FLOATS * 4)    // 30720
#define BSTRIDE_U32 132       // u32 per B row: 64 hi pairs + 64 lo pairs + 4 pad
#define B_BYTES  (32 * BSTRIDE_U32 * 4)       // 16896
#define SMEM_BYTES (A_BYTES + B_BYTES)        // 47616

// m16n8k16 bf16 mma: D += A*B, fp32 accumulate.
__device__ __forceinline__ void mma_bf16(float* d, uint32_t a0, uint32_t a1,
                                         uint32_t a2, uint32_t a3,
                                         uint32_t b0, uint32_t b1) {
    asm("mma.sync.aligned.m16n8k16.row.col.f32.bf16.bf16.f32 "
        "{%0,%1,%2,%3}, {%4,%5,%6,%7}, {%8,%9}, {%0,%1,%2,%3};"
        : "+f"(d[0]), "+f"(d[1]), "+f"(d[2]), "+f"(d[3])
        : "r"(a0), "r"(a1), "r"(a2), "r"(a3), "r"(b0), "r"(b1));
}

// pack bf16x2: x -> low half, y -> high half
__device__ __forceinline__ uint32_t pack_bf16(float x, float y) {
    uint32_t d;
    asm("cvt.rn.bf16x2.f32 %0, %1, %2;" : "=r"(d) : "f"(y), "f"(x));
    return d;
}
// Split fp32 pair into bf16 hi pack + bf16 residual pack (residual exact in fp32).
__device__ __forceinline__ void split_pair(float x, float y, uint32_t& h, uint32_t& l) {
    h = pack_bf16(x, y);
    float hx = __uint_as_float(h << 16);
    float hy = __uint_as_float(h & 0xFFFF0000u);
    l = pack_bf16(x - hx, y - hy);
}

__device__ __forceinline__ uint32_t smem_u32adr(const void* p) {
    uint32_t a;
    asm("{ .reg .u64 t; cvta.to.shared.u64 t, %1; cvt.u32.u64 %0, t; }" : "=r"(a) : "l"(p));
    return a;
}
__device__ __forceinline__ void cp16(uint32_t dst, const void* src) {
    asm volatile("cp.async.cg.shared.global [%0], [%1], 16;" :: "r"(dst), "l"(src));
}
#define CP_COMMIT()  asm volatile("cp.async.commit_group;" ::: "memory")
#define CP_WAIT(n)   asm volatile("cp.async.wait_group %0;" :: "n"(n) : "memory")

// Per CTA: out[128,32] = W[idx[b]] @ x[b] via 3xBF16-split m16n8k16 mma.sync.
// D = ah*bh + al*bh + ah*bl. A (W) streamed fp32 via 3-stage cp.async ring,
// split per-warp in registers (warp-exclusive rows -> no redundancy).
// B (x) staged ONCE pre-split as packed bf16 hi/lo pairs (removes the 4x
// redundant per-warp B splits from the hot loop). Index dtype (int32 vs
// silently-downcast int64) resolved inline per CTA from odd-word evidence.
__global__ void __launch_bounds__(THREADS, 4) bmm_mma_kernel(
    const float* __restrict__ inp,
    const float* __restrict__ W,
    const int*   __restrict__ idx_raw,
    float* __restrict__ out)
{
    extern __shared__ char smem[];
    float*    As = (float*)smem;                 // 3 chunk buffers, fp32
    uint32_t* Bs = (uint32_t*)(smem + A_BYTES);  // [32 n][132 u32]: hi(0..63) lo(64..127)

    const int blk = blockIdx.x;
    const int tid = threadIdx.x;
    const int wid = tid >> 5;
    const int lid = tid & 31;
    const int gid = lid >> 2;         // groupID 0..7
    const int tig = lid & 3;          // thread-in-group 0..3

    // ---- Inline index resolution: int64 (odd words all 0) vs int32 ----
    int odd = idx_raw[1] | idx_raw[3] | idx_raw[5] | idx_raw[7] | idx_raw[9];
    int g = odd ? idx_raw[blk] : idx_raw[2 * blk];
    g = (g < 0) ? 0 : ((g >= 1024) ? 1023 : g);

    const float* Wg = W + (long long)g * (NBLK * NBLK);

    // One A chunk = 128 rows x 16 floats; 4 cp.async per thread.
    #define ISSUE_CHUNK(ck, buf) do {                                            \
        const float* srcb = Wg + (ck) * CHUNK_K;                                 \
        float* dstb = As + (buf) * ACH_FLOATS;                                   \
        _Pragma("unroll")                                                        \
        for (int it = 0; it < 4; ++it) {                                         \
            int c = tid + THREADS * it;                                          \
            int row = c >> 2, slot = c & 3;                                      \
            cp16(smem_u32adr(dstb + row * ASTRIDE + slot * 4),                   \
                 srcb + row * NBLK + slot * 4);                                  \
        }                                                                        \
        CP_COMMIT();                                                             \
    } while (0)

    ISSUE_CHUNK(0, 0);
    ISSUE_CHUNK(1, 1);

    // ---- Stage B pre-split: x[k][f] -> Bs[n][pair] bf16 hi/lo ----
    // q in [0,512): pair p = q>>3 (k = 2p,2p+1), n-base = (q&7)*4.
    {
        const float* xb = inp + (long long)blk * NBLK * FEAT;
        #pragma unroll
        for (int it = 0; it < 4; ++it) {
            int q  = tid + THREADS * it;
            int p  = q >> 3;
            int nb = (q & 7) * 4;
            float4 v0 = *(const float4*)(xb + (2 * p)     * FEAT + nb);
            float4 v1 = *(const float4*)(xb + (2 * p + 1) * FEAT + nb);
            const float e0[4] = {v0.x, v0.y, v0.z, v0.w};
            const float e1[4] = {v1.x, v1.y, v1.z, v1.w};
            #pragma unroll
            for (int j = 0; j < 4; ++j) {
                uint32_t h, l;
                split_pair(e0[j], e1[j], h, l);
                Bs[(nb + j) * BSTRIDE_U32 + p]      = h;
                Bs[(nb + j) * BSTRIDE_U32 + 64 + p] = l;
            }
        }
    }

    // Warp w computes rows [w*32, w*32+32) x all 32 cols: 2 m-tiles x 4 n-tiles.
    const int R = wid * 32;

    float d[2][4][4];
    #pragma unroll
    for (int mt = 0; mt < 2; ++mt)
        #pragma unroll
        for (int nt = 0; nt < 4; ++nt)
            #pragma unroll
            for (int e = 0; e < 4; ++e) d[mt][nt][e] = 0.0f;

    const uint32_t a_row = R + gid;
    // B fragment pointers: n = nt*8+gid, pairs (ck*8+tig) and (ck*8+tig+4)
    const uint32_t* b_base = Bs + gid * BSTRIDE_U32 + tig;

    #pragma unroll
    for (int ck = 0; ck < NCHUNK; ++ck) {
        if (ck < NCHUNK - 1) { CP_WAIT(1); } else { CP_WAIT(0); }
        __syncthreads();   // chunk ck visible; buf (ck+2)%3's old chunk consumed

        if (ck + 2 < NCHUNK) ISSUE_CHUNK(ck + 2, (ck + 2) % NSTAGE);

        // ---- A fragments: split fp32 -> bf16 hi/lo in registers ----
        const float* a_base = As + (ck % NSTAGE) * ACH_FLOATS
                              + a_row * ASTRIDE + 2 * tig;
        uint32_t ah[2][4], al[2][4];
        #pragma unroll
        for (int mt = 0; mt < 2; ++mt) {
            const float* p = a_base + mt * (16 * ASTRIDE);
            float2 v0 = *(const float2*)(p);                    // (r0,   k0,k0+1)
            float2 v1 = *(const float2*)(p + 8 * ASTRIDE);      // (r0+8, k0,k0+1)
            float2 v2 = *(const float2*)(p + 8);                // (r0,   k0+8,k0+9)
            float2 v3 = *(const float2*)(p + 8 * ASTRIDE + 8);  // (r0+8, k0+8,k0+9)
            split_pair(v0.x, v0.y, ah[mt][0], al[mt][0]);
            split_pair(v1.x, v1.y, ah[mt][1], al[mt][1]);
            split_pair(v2.x, v2.y, ah[mt][2], al[mt][2]);
            split_pair(v3.x, v3.y, ah[mt][3], al[mt][3]);
        }

        // ---- B fragments: direct LDS.32 of pre-split packs (conflict-free) ----
        uint32_t bh[4][2], bl[4][2];
        const int poff = ck * 8;
        #pragma unroll
        for (int nt = 0; nt < 4; ++nt) {
            const uint32_t* p = b_base + nt * 8 * BSTRIDE_U32 + poff;
            bh[nt][0] = p[0];
            bh[nt][1] = p[4];
            bl[nt][0] = p[64];
            bl[nt][1] = p[68];
        }

        // ---- Pass-major emission: hh, then al*bh, then ah*bl ----
        #pragma unroll
        for (int mt = 0; mt < 2; ++mt)
            #pragma unroll
            for (int nt = 0; nt < 4; ++nt)
                mma_bf16(d[mt][nt], ah[mt][0], ah[mt][1], ah[mt][2], ah[mt][3],
                         bh[nt][0], bh[nt][1]);
        #pragma unroll
        for (int mt = 0; mt < 2; ++mt)
            #pragma unroll
            for (int nt = 0; nt < 4; ++nt)
                mma_bf16(d[mt][nt], al[mt][0], al[mt][1], al[mt][2], al[mt][3],
                         bh[nt][0], bh[nt][1]);
        #pragma unroll
        for (int mt = 0; mt < 2; ++mt)
            #pragma unroll
            for (int nt = 0; nt < 4; ++nt)
                mma_bf16(d[mt][nt], ah[mt][0], ah[mt][1], ah[mt][2], ah[mt][3],
                         bl[nt][0], bl[nt][1]);
    }

    // ---- Epilogue: write D fragments straight to gmem (float2 per pair) ----
    float* ob = out + (long long)blk * NBLK * FEAT;
    #pragma unroll
    for (int mt = 0; mt < 2; ++mt) {
        const int r0 = R + mt * 16 + gid;
        #pragma unroll
        for (int nt = 0; nt < 4; ++nt) {
            const int c = nt * 8 + tig * 2;
            *(float2*)(ob + r0 * FEAT + c)       = make_float2(d[mt][nt][0], d[mt][nt][1]);
            *(float2*)(ob + (r0 + 8) * FEAT + c) = make_float2(d[mt][nt][2], d[mt][nt][3]);
        }
    }
}

extern "C" void kernel_launch(void* const* d_in, const int* in_sizes, int n_in,
                              void* d_out, int out_size) {
    // Select pointers by element count (robust to metadata ordering).
    const float* inp = nullptr;
    const float* W   = nullptr;
    const void*  idx = nullptr;
    for (int i = 0; i < n_in; ++i) {
        if      (in_sizes[i] == 4194304)  inp = (const float*)d_in[i];
        else if (in_sizes[i] == 16777216) W   = (const float*)d_in[i];
        else if (in_sizes[i] == 1024)     idx = d_in[i];
    }

    cudaFuncSetAttribute(bmm_mma_kernel, cudaFuncAttributeMaxDynamicSharedMemorySize,
                         SMEM_BYTES);
    bmm_mma_kernel<<<NBATCH, THREADS, SMEM_BYTES>>>(inp, W, (const int*)idx,
                                                    (float*)d_out);
}

// round 13
// speedup vs baseline: 1.3685x; 1.1505x over previous
#include <cuda_runtime.h>
#include <cstdint>

#define NBLK    128
#define FEAT    32
#define THREADS 128
#define NBATCH  1024

#define NCHUNK   8            // k-chunks of 16 (one m16n8k16 step each)
#define CHUNK_K  16
#define ASTRIDE  24           // floats per A chunk row (16 + 8 pad): frag float2 loads conflict-free
#define AW_FLOATS (32 * ASTRIDE)          // 768 floats per warp per stage
#define NSTAGE   3
#define A_BYTES  (4 * NSTAGE * AW_FLOATS * 4)   // 36864
#define BSTRIDE_U32 132       // u32 per B row: 64 hi pairs + 64 lo pairs + 4 pad
#define B_BYTES  (32 * BSTRIDE_U32 * 4)         // 16896
#define SMEM_BYTES (A_BYTES + B_BYTES)          // 53760

// m16n8k16 bf16 mma: D += A*B, fp32 accumulate.
__device__ __forceinline__ void mma_bf16(float* d, uint32_t a0, uint32_t a1,
                                         uint32_t a2, uint32_t a3,
                                         uint32_t b0, uint32_t b1) {
    asm("mma.sync.aligned.m16n8k16.row.col.f32.bf16.bf16.f32 "
        "{%0,%1,%2,%3}, {%4,%5,%6,%7}, {%8,%9}, {%0,%1,%2,%3};"
        : "+f"(d[0]), "+f"(d[1]), "+f"(d[2]), "+f"(d[3])
        : "r"(a0), "r"(a1), "r"(a2), "r"(a3), "r"(b0), "r"(b1));
}

// pack bf16x2: x -> low half, y -> high half
__device__ __forceinline__ uint32_t pack_bf16(float x, float y) {
    uint32_t d;
    asm("cvt.rn.bf16x2.f32 %0, %1, %2;" : "=r"(d) : "f"(y), "f"(x));
    return d;
}
// Split fp32 pair into bf16 hi pack + bf16 residual pack (residual exact in fp32).
__device__ __forceinline__ void split_pair(float x, float y, uint32_t& h, uint32_t& l) {
    h = pack_bf16(x, y);
    float hx = __uint_as_float(h << 16);
    float hy = __uint_as_float(h & 0xFFFF0000u);
    l = pack_bf16(x - hx, y - hy);
}

__device__ __forceinline__ uint32_t smem_u32adr(const void* p) {
    uint32_t a;
    asm("{ .reg .u64 t; cvta.to.shared.u64 t, %1; cvt.u32.u64 %0, t; }" : "=r"(a) : "l"(p));
    return a;
}
__device__ __forceinline__ void cp16(uint32_t dst, const void* src) {
    asm volatile("cp.async.cg.shared.global [%0], [%1], 16;" :: "r"(dst), "l"(src));
}
#define CP_COMMIT()  asm volatile("cp.async.commit_group;" ::: "memory")
#define CP_WAIT(n)   asm volatile("cp.async.wait_group %0;" :: "n"(n) : "memory")

// Per CTA: out[128,32] = W[idx[b]] @ x[b] via 3xBF16-split m16n8k16 mma.sync.
// D = ah*bh + al*bh + ah*bl. Each WARP owns rows [32w,32w+32) end-to-end: it
// streams its own A rows through a private 3-stage cp.async ring and waits on
// its own groups -> ZERO CTA-wide barriers in the main loop (warps slide
// freely; 16 staggered warp-pipelines/SM hide DRAM latency). B (x) staged once
// pre-split as bf16 hi/lo packs. Index dtype resolved inline.
__global__ void __launch_bounds__(THREADS, 4) bmm_mma_kernel(
    const float* __restrict__ inp,
    const float* __restrict__ W,
    const int*   __restrict__ idx_raw,
    float* __restrict__ out)
{
    extern __shared__ char smem[];
    float*    As = (float*)smem;                 // per-warp: 3 stages x 768 floats
    uint32_t* Bs = (uint32_t*)(smem + A_BYTES);  // [32 n][132 u32]: hi(0..63) lo(64..127)

    const int blk = blockIdx.x;
    const int tid = threadIdx.x;
    const int wid = tid >> 5;
    const int lid = tid & 31;
    const int gid = lid >> 2;         // groupID 0..7
    const int tig = lid & 3;          // thread-in-group 0..3

    // ---- Inline index resolution: int64 (odd words all 0) vs int32 ----
    int odd = idx_raw[1] | idx_raw[3] | idx_raw[5] | idx_raw[7] | idx_raw[9];
    int g = odd ? idx_raw[blk] : idx_raw[2 * blk];
    g = (g < 0) ? 0 : ((g >= 1024) ? 1023 : g);

    // Warp-private A region and gmem row base (warp w owns rows [32w, 32w+32)).
    const float* Wg = W + (long long)g * (NBLK * NBLK) + (wid * 32) * NBLK;
    float* Aw = As + wid * (NSTAGE * AW_FLOATS);

    // One warp-chunk = 32 rows x 16 floats = 128 x 16B; 4 cp.async per lane.
    #define ISSUE_CHUNK(ck, buf) do {                                            \
        const float* srcb = Wg + (ck) * CHUNK_K;                                 \
        float* dstb = Aw + (buf) * AW_FLOATS;                                    \
        _Pragma("unroll")                                                        \
        for (int it = 0; it < 4; ++it) {                                         \
            int c = lid + 32 * it;                                               \
            int row = c >> 2, slot = c & 3;                                      \
            cp16(smem_u32adr(dstb + row * ASTRIDE + slot * 4),                   \
                 srcb + row * NBLK + slot * 4);                                  \
        }                                                                        \
        CP_COMMIT();                                                             \
    } while (0)

    ISSUE_CHUNK(0, 0);
    ISSUE_CHUNK(1, 1);

    // ---- Stage B pre-split: x[k][f] -> Bs[n][pair] bf16 hi/lo ----
    {
        const float* xb = inp + (long long)blk * NBLK * FEAT;
        #pragma unroll
        for (int it = 0; it < 4; ++it) {
            int q  = tid + THREADS * it;
            int p  = q >> 3;
            int nb = (q & 7) * 4;
            float4 v0 = *(const float4*)(xb + (2 * p)     * FEAT + nb);
            float4 v1 = *(const float4*)(xb + (2 * p + 1) * FEAT + nb);
            const float e0[4] = {v0.x, v0.y, v0.z, v0.w};
            const float e1[4] = {v1.x, v1.y, v1.z, v1.w};
            #pragma unroll
            for (int j = 0; j < 4; ++j) {
                uint32_t h, l;
                split_pair(e0[j], e1[j], h, l);
                Bs[(nb + j) * BSTRIDE_U32 + p]      = h;
                Bs[(nb + j) * BSTRIDE_U32 + 64 + p] = l;
            }
        }
    }
    __syncthreads();   // the ONLY CTA-wide barrier: B visible to all warps

    float d[2][4][4];
    #pragma unroll
    for (int mt = 0; mt < 2; ++mt)
        #pragma unroll
        for (int nt = 0; nt < 4; ++nt)
            #pragma unroll
            for (int e = 0; e < 4; ++e) d[mt][nt][e] = 0.0f;

    // B fragment pointers: n = nt*8+gid, pairs (ck*8+tig) and (+4)
    const uint32_t* b_base = Bs + gid * BSTRIDE_U32 + tig;

    #pragma unroll
    for (int ck = 0; ck < NCHUNK; ++ck) {
        if (ck < NCHUNK - 1) { CP_WAIT(1); } else { CP_WAIT(0); }
        __syncwarp();     // cross-lane smem visibility within the warp

        if (ck + 2 < NCHUNK) ISSUE_CHUNK(ck + 2, (ck + 2) % NSTAGE);

        // ---- A fragments: conflict-free float2 LDS, split fp32 -> bf16 hi/lo ----
        const float* a_base = Aw + (ck % NSTAGE) * AW_FLOATS + gid * ASTRIDE + 2 * tig;
        uint32_t ah[2][4], al[2][4];
        #pragma unroll
        for (int mt = 0; mt < 2; ++mt) {
            const float* p = a_base + mt * (16 * ASTRIDE);
            float2 v0 = *(const float2*)(p);                    // (r0,   k0,k0+1)
            float2 v1 = *(const float2*)(p + 8 * ASTRIDE);      // (r0+8, k0,k0+1)
            float2 v2 = *(const float2*)(p + 8);                // (r0,   k0+8,k0+9)
            float2 v3 = *(const float2*)(p + 8 * ASTRIDE + 8);  // (r0+8, k0+8,k0+9)
            split_pair(v0.x, v0.y, ah[mt][0], al[mt][0]);
            split_pair(v1.x, v1.y, ah[mt][1], al[mt][1]);
            split_pair(v2.x, v2.y, ah[mt][2], al[mt][2]);
            split_pair(v3.x, v3.y, ah[mt][3], al[mt][3]);
        }

        // ---- B fragments: direct LDS.32 of pre-split packs (conflict-free) ----
        uint32_t bh[4][2], bl[4][2];
        const int poff = ck * 8;
        #pragma unroll
        for (int nt = 0; nt < 4; ++nt) {
            const uint32_t* p = b_base + nt * 8 * BSTRIDE_U32 + poff;
            bh[nt][0] = p[0];
            bh[nt][1] = p[4];
            bl[nt][0] = p[64];
            bl[nt][1] = p[68];
        }

        // ---- Pass-major emission: hh, then al*bh, then ah*bl ----
        #pragma unroll
        for (int mt = 0; mt < 2; ++mt)
            #pragma unroll
            for (int nt = 0; nt < 4; ++nt)
                mma_bf16(d[mt][nt], ah[mt][0], ah[mt][1], ah[mt][2], ah[mt][3],
                         bh[nt][0], bh[nt][1]);
        #pragma unroll
        for (int mt = 0; mt < 2; ++mt)
            #pragma unroll
            for (int nt = 0; nt < 4; ++nt)
                mma_bf16(d[mt][nt], al[mt][0], al[mt][1], al[mt][2], al[mt][3],
                         bh[nt][0], bh[nt][1]);
        #pragma unroll
        for (int mt = 0; mt < 2; ++mt)
            #pragma unroll
            for (int nt = 0; nt < 4; ++nt)
                mma_bf16(d[mt][nt], ah[mt][0], ah[mt][1], ah[mt][2], ah[mt][3],
                         bl[nt][0], bl[nt][1]);
    }

    // ---- Epilogue: write D fragments straight to gmem (float2 per pair) ----
    float* ob = out + (long long)blk * NBLK * FEAT;
    #pragma unroll
    for (int mt = 0; mt < 2; ++mt) {
        const int r0 = wid * 32 + mt * 16 + gid;
        #pragma unroll
        for (int nt = 0; nt < 4; ++nt) {
            const int c = nt * 8 + tig * 2;
            *(float2*)(ob + r0 * FEAT + c)       = make_float2(d[mt][nt][0], d[mt][nt][1]);
            *(float2*)(ob + (r0 + 8) * FEAT + c) = make_float2(d[mt][nt][2], d[mt][nt][3]);
        }
    }
}

extern "C" void kernel_launch(void* const* d_in, const int* in_sizes, int n_in,
                              void* d_out, int out_size) {
    // Select pointers by element count (robust to metadata ordering).
    const float* inp = nullptr;
    const float* W   = nullptr;
    const void*  idx = nullptr;
    for (int i = 0; i < n_in; ++i) {
        if      (in_sizes[i] == 4194304)  inp = (const float*)d_in[i];
        else if (in_sizes[i] == 16777216) W   = (const float*)d_in[i];
        else if (in_sizes[i] == 1024)     idx = d_in[i];
    }

    cudaFuncSetAttribute(bmm_mma_kernel, cudaFuncAttributeMaxDynamicSharedMemorySize,
                         SMEM_BYTES);
    bmm_mma_kernel<<<NBATCH, THREADS, SMEM_BYTES>>>(inp, W, (const int*)idx,
                                                    (float*)d_out);
}

// round 14
// speedup vs baseline: 1.4785x; 1.0804x over previous
#include <cuda_runtime.h>
#include <cstdint>

#define NBLK    128
#define FEAT    32
#define THREADS 128
#define NBATCH  1024

#define NCHUNK   8            // k-chunks of 16 (one m16n8k16 step each)
#define CHUNK_K  16
#define AW_FLOATS 512         // 32 rows x 16 floats, XOR-swizzled, NO pad
#define NSTAGE   3
#define A_BYTES  (4 * NSTAGE * AW_FLOATS * 4)   // 24576
#define BSTRIDE_U32 132       // u32 per B row: 64 hi pairs + 64 lo pairs + 4 pad
#define B_BYTES  (32 * BSTRIDE_U32 * 4)         // 16896
#define SMEM_BYTES (A_BYTES + B_BYTES)          // 41472 -> 5 CTAs/SM

// m16n8k16 bf16 mma: D += A*B, fp32 accumulate.
__device__ __forceinline__ void mma_bf16(float* d, uint32_t a0, uint32_t a1,
                                         uint32_t a2, uint32_t a3,
                                         uint32_t b0, uint32_t b1) {
    asm("mma.sync.aligned.m16n8k16.row.col.f32.bf16.bf16.f32 "
        "{%0,%1,%2,%3}, {%4,%5,%6,%7}, {%8,%9}, {%0,%1,%2,%3};"
        : "+f"(d[0]), "+f"(d[1]), "+f"(d[2]), "+f"(d[3])
        : "r"(a0), "r"(a1), "r"(a2), "r"(a3), "r"(b0), "r"(b1));
}

// pack bf16x2: x -> low half, y -> high half
__device__ __forceinline__ uint32_t pack_bf16(float x, float y) {
    uint32_t d;
    asm("cvt.rn.bf16x2.f32 %0, %1, %2;" : "=r"(d) : "f"(y), "f"(x));
    return d;
}
// Split fp32 pair into bf16 hi pack + bf16 residual pack (residual exact in fp32).
__device__ __forceinline__ void split_pair(float x, float y, uint32_t& h, uint32_t& l) {
    h = pack_bf16(x, y);
    float hx = __uint_as_float(h << 16);
    float hy = __uint_as_float(h & 0xFFFF0000u);
    l = pack_bf16(x - hx, y - hy);
}

__device__ __forceinline__ uint32_t smem_u32adr(const void* p) {
    uint32_t a;
    asm("{ .reg .u64 t; cvta.to.shared.u64 t, %1; cvt.u32.u64 %0, t; }" : "=r"(a) : "l"(p));
    return a;
}
__device__ __forceinline__ void cp16(uint32_t dst, const void* src) {
    asm volatile("cp.async.cg.shared.global [%0], [%1], 16;" :: "r"(dst), "l"(src));
}
#define CP_COMMIT()  asm volatile("cp.async.commit_group;" ::: "memory")
#define CP_WAIT(n)   asm volatile("cp.async.wait_group %0;" :: "n"(n) : "memory")

// Per CTA: out[128,32] = W[idx[b]] @ x[b] via 3xBF16-split m16n8k16 mma.sync.
// D = ah*bh + al*bh + ah*bl. Warp-private 3-stage cp.async rings (zero in-loop
// CTA barriers). A chunk buffers are PAD-FREE with XOR swizzle
//   phys_word = row*16 + (col ^ ((row&3)<<2))
// (staging STS.128: 4-phase min; frag LDS.64: 2-phase min; swizzle term is
// per-thread constant since +8/+16 row offsets preserve row&3).
// 41.5KB smem -> 5 CTAs/SM (waves 1.73 -> 1.38). B pre-split once as bf16 packs.
__global__ void __launch_bounds__(THREADS, 5) bmm_mma_kernel(
    const float* __restrict__ inp,
    const float* __restrict__ W,
    const int*   __restrict__ idx_raw,
    float* __restrict__ out)
{
    extern __shared__ char smem[];
    float*    As = (float*)smem;                 // per-warp: 3 stages x 512 floats
    uint32_t* Bs = (uint32_t*)(smem + A_BYTES);  // [32 n][132 u32]: hi(0..63) lo(64..127)

    const int blk = blockIdx.x;
    const int tid = threadIdx.x;
    const int wid = tid >> 5;
    const int lid = tid & 31;
    const int gid = lid >> 2;         // groupID 0..7
    const int tig = lid & 3;          // thread-in-group 0..3

    // ---- Inline index resolution: int64 (odd words all 0) vs int32 ----
    int odd = idx_raw[1] | idx_raw[3] | idx_raw[5] | idx_raw[7] | idx_raw[9];
    int g = odd ? idx_raw[blk] : idx_raw[2 * blk];
    g = (g < 0) ? 0 : ((g >= 1024) ? 1023 : g);

    // Warp-private A region and gmem row base (warp w owns rows [32w, 32w+32)).
    const float* Wg = W + (long long)g * (NBLK * NBLK) + (wid * 32) * NBLK;
    float* Aw = As + wid * (NSTAGE * AW_FLOATS);

    // One warp-chunk = 32 rows x 16 floats; 4 cp.async per lane, swizzled dst.
    #define ISSUE_CHUNK(ck, buf) do {                                            \
        const float* srcb = Wg + (ck) * CHUNK_K;                                 \
        float* dstb = Aw + (buf) * AW_FLOATS;                                    \
        _Pragma("unroll")                                                        \
        for (int it = 0; it < 4; ++it) {                                         \
            int c = lid + 32 * it;                                               \
            int row = c >> 2, slot = c & 3;                                      \
            cp16(smem_u32adr(dstb + row * 16 + ((slot ^ (row & 3)) << 2)),       \
                 srcb + row * NBLK + slot * 4);                                  \
        }                                                                        \
        CP_COMMIT();                                                             \
    } while (0)

    ISSUE_CHUNK(0, 0);
    ISSUE_CHUNK(1, 1);

    // ---- Stage B pre-split: x[k][f] -> Bs[n][pair] bf16 hi/lo ----
    {
        const float* xb = inp + (long long)blk * NBLK * FEAT;
        #pragma unroll
        for (int it = 0; it < 4; ++it) {
            int q  = tid + THREADS * it;
            int p  = q >> 3;
            int nb = (q & 7) * 4;
            float4 v0 = *(const float4*)(xb + (2 * p)     * FEAT + nb);
            float4 v1 = *(const float4*)(xb + (2 * p + 1) * FEAT + nb);
            const float e0[4] = {v0.x, v0.y, v0.z, v0.w};
            const float e1[4] = {v1.x, v1.y, v1.z, v1.w};
            #pragma unroll
            for (int j = 0; j < 4; ++j) {
                uint32_t h, l;
                split_pair(e0[j], e1[j], h, l);
                Bs[(nb + j) * BSTRIDE_U32 + p]      = h;
                Bs[(nb + j) * BSTRIDE_U32 + 64 + p] = l;
            }
        }
    }
    __syncthreads();   // the ONLY CTA-wide barrier: B visible to all warps

    float d[2][4][4];
    #pragma unroll
    for (int mt = 0; mt < 2; ++mt)
        #pragma unroll
        for (int nt = 0; nt < 4; ++nt)
            #pragma unroll
            for (int e = 0; e < 4; ++e) d[mt][nt][e] = 0.0f;

    // Per-thread constant swizzled column offsets within an A row block:
    const int acol_lo = (2 * tig) ^ ((gid & 3) << 2);   // cols 2tig,2tig+1
    const int acol_hi = acol_lo ^ 8;                    // cols 2tig+8,2tig+9
    // B fragment pointers: n = nt*8+gid, pairs (ck*8+tig) and (+4)
    const uint32_t* b_base = Bs + gid * BSTRIDE_U32 + tig;

    #pragma unroll
    for (int ck = 0; ck < NCHUNK; ++ck) {
        if (ck < NCHUNK - 1) { CP_WAIT(1); } else { CP_WAIT(0); }
        __syncwarp();     // cross-lane smem visibility within the warp

        if (ck + 2 < NCHUNK) ISSUE_CHUNK(ck + 2, (ck + 2) % NSTAGE);

        // ---- A fragments: swizzled float2 LDS (2-phase min), bf16 split ----
        const float* a_stage = Aw + (ck % NSTAGE) * AW_FLOATS + gid * 16;
        uint32_t ah[2][4], al[2][4];
        #pragma unroll
        for (int mt = 0; mt < 2; ++mt) {
            const float* p = a_stage + mt * (16 * 16);          // +16 rows
            float2 v0 = *(const float2*)(p + acol_lo);          // (r0,   k0,k0+1)
            float2 v1 = *(const float2*)(p + 128 + acol_lo);    // (r0+8, k0,k0+1)
            float2 v2 = *(const float2*)(p + acol_hi);          // (r0,   k0+8,+9)
            float2 v3 = *(const float2*)(p + 128 + acol_hi);    // (r0+8, k0+8,+9)
            split_pair(v0.x, v0.y, ah[mt][0], al[mt][0]);
            split_pair(v1.x, v1.y, ah[mt][1], al[mt][1]);
            split_pair(v2.x, v2.y, ah[mt][2], al[mt][2]);
            split_pair(v3.x, v3.y, ah[mt][3], al[mt][3]);
        }

        // ---- B fragments: direct LDS.32 of pre-split packs (conflict-free) ----
        uint32_t bh[4][2], bl[4][2];
        const int poff = ck * 8;
        #pragma unroll
        for (int nt = 0; nt < 4; ++nt) {
            const uint32_t* p = b_base + nt * 8 * BSTRIDE_U32 + poff;
            bh[nt][0] = p[0];
            bh[nt][1] = p[4];
            bl[nt][0] = p[64];
            bl[nt][1] = p[68];
        }

        // ---- Pass-major emission: hh, then al*bh, then ah*bl ----
        #pragma unroll
        for (int mt = 0; mt < 2; ++mt)
            #pragma unroll
            for (int nt = 0; nt < 4; ++nt)
                mma_bf16(d[mt][nt], ah[mt][0], ah[mt][1], ah[mt][2], ah[mt][3],
                         bh[nt][0], bh[nt][1]);
        #pragma unroll
        for (int mt = 0; mt < 2; ++mt)
            #pragma unroll
            for (int nt = 0; nt < 4; ++nt)
                mma_bf16(d[mt][nt], al[mt][0], al[mt][1], al[mt][2], al[mt][3],
                         bh[nt][0], bh[nt][1]);
        #pragma unroll
        for (int mt = 0; mt < 2; ++mt)
            #pragma unroll
            for (int nt = 0; nt < 4; ++nt)
                mma_bf16(d[mt][nt], ah[mt][0], ah[mt][1], ah[mt][2], ah[mt][3],
                         bl[nt][0], bl[nt][1]);
    }

    // ---- Epilogue: write D fragments straight to gmem (float2 per pair) ----
    float* ob = out + (long long)blk * NBLK * FEAT;
    #pragma unroll
    for (int mt = 0; mt < 2; ++mt) {
        const int r0 = wid * 32 + mt * 16 + gid;
        #pragma unroll
        for (int nt = 0; nt < 4; ++nt) {
            const int c = nt * 8 + tig * 2;
            *(float2*)(ob + r0 * FEAT + c)       = make_float2(d[mt][nt][0], d[mt][nt][1]);
            *(float2*)(ob + (r0 + 8) * FEAT + c) = make_float2(d[mt][nt][2], d[mt][nt][3]);
        }
    }
}

extern "C" void kernel_launch(void* const* d_in, const int* in_sizes, int n_in,
                              void* d_out, int out_size) {
    // Select pointers by element count (robust to metadata ordering).
    const float* inp = nullptr;
    const float* W   = nullptr;
    const void*  idx = nullptr;
    for (int i = 0; i < n_in; ++i) {
        if      (in_sizes[i] == 4194304)  inp = (const float*)d_in[i];
        else if (in_sizes[i] == 16777216) W   = (const float*)d_in[i];
        else if (in_sizes[i] == 1024)     idx = d_in[i];
    }

    cudaFuncSetAttribute(bmm_mma_kernel, cudaFuncAttributeMaxDynamicSharedMemorySize,
                         SMEM_BYTES);
    bmm_mma_kernel<<<NBATCH, THREADS, SMEM_BYTES>>>(inp, W, (const int*)idx,
                                                    (float*)d_out);
}